// round 6
// baseline (speedup 1.0000x reference)
#include <cuda_runtime.h>
#include <cstdint>

#define HW 3136
#define EPS 1e-5f
#define NPATCH 3136   // 16 b * 4 g * 7 * 7

// Scratch (device globals: no runtime allocation allowed)
__device__ float g_mid1[16 * 128 * HW];
__device__ float g_mid2[16 * 128 * HW];
__device__ int g_nact;
__device__ int g_list[NPATCH];  // actives [0,nact), inactives [nact,NPATCH) (from back)

// ---------------------------------------------------------------------------
// prep: compact active patches to front of list, inactive to back
// ---------------------------------------------------------------------------
__global__ void prep(const float* __restrict__ mask) {
    __shared__ int s_act, s_inact;
    if (threadIdx.x == 0) { s_act = 0; s_inact = 0; }
    __syncthreads();
    for (int i = threadIdx.x; i < NPATCH; i += blockDim.x) {
        // mask layout [b][g][7][7] is exactly linear index i
        if (mask[i] != 0.f) {
            int p = atomicAdd(&s_act, 1);
            g_list[p] = i;
        } else {
            int p = atomicAdd(&s_inact, 1);
            g_list[NPATCH - 1 - p] = i;
        }
    }
    __syncthreads();
    if (threadIdx.x == 0) g_nact = s_act;
}

// ---------------------------------------------------------------------------
// zero mid1 (k2 halo reads may touch inactive patches)
// ---------------------------------------------------------------------------
__global__ void zero_mid1() {
    const int n4 = (16 * 128 * HW) / 4;  // float4 count
    float4* p = (float4*)g_mid1;
    float4 z = make_float4(0.f, 0.f, 0.f, 0.f);
    for (int i = blockIdx.x * blockDim.x + threadIdx.x; i < n4; i += gridDim.x * blockDim.x)
        p[i] = z;
}

// Common decode: 224 threads = 7 warps; each warp owns one patch from g_list.
// lane: r=l>>2 (row in patch), cp=l&3 (col pair); thread owns 2 adjacent pixels.

// ---------------------------------------------------------------------------
// K1: 1x1 conv (128 -> 8 oc per block) + BN1 + ReLU + mask premult
// grid = 448*4 (qc chunks); active patches only
// ---------------------------------------------------------------------------
__global__ __launch_bounds__(224, 5) void k1(const float* __restrict__ x,
                                             const float* __restrict__ mask,
                                             const float* __restrict__ w1,
                                             const float* __restrict__ bg1,
                                             const float* __restrict__ bb1,
                                             const float* __restrict__ bm1,
                                             const float* __restrict__ bv1) {
    __shared__ __align__(16) float ws[4096];  // [g][ic][8]

    const int t = threadIdx.x, blk = blockIdx.x;
    const int qc = blk & 3;
    const int bp = blk >> 2;
    const int nact = g_nact;
    if (bp * 7 >= nact) return;

    for (int e = t; e < 4096; e += 224) {
        int gg = e >> 10;
        int rem = e & 1023;
        int j = rem >> 7, ic = rem & 127;
        ws[gg * 1024 + ic * 8 + j] = w1[(gg * 32 + qc * 8 + j) * 128 + ic];
    }
    __syncthreads();

    const int w = t >> 5, l = t & 31;
    const int base = bp * 7 + w;
    if (base >= nact) return;

    const int packed = g_list[base];
    const int pc = packed % 7;
    const int rest = packed / 7;
    const int pr = rest % 7;
    const int bgp = rest / 7;
    const int g = bgp & 3, b = bgp >> 2;
    const float m = mask[packed];

    const int r = l >> 2, cp = l & 3;
    const int grow = pr * 8 + r;
    const int col = pc * 8 + cp * 2;

    const float* xp = x + (size_t)(b * 512 + g * 128) * HW + grow * 56 + col;
    float* op = g_mid1 + (size_t)(b * 128 + g * 32 + qc * 8) * HW + grow * 56 + col;
    const float* wsg = ws + g * 1024;

    float a0[8], a1[8];
#pragma unroll
    for (int j = 0; j < 8; j++) { a0[j] = 0.f; a1[j] = 0.f; }

    for (int ic0 = 0; ic0 < 128; ic0 += 8) {
        float2 xv[8];
#pragma unroll
        for (int u = 0; u < 8; u++)
            xv[u] = *(const float2*)(xp + (size_t)(ic0 + u) * HW);
#pragma unroll
        for (int u = 0; u < 8; u++) {
            const float4* wp = (const float4*)(wsg + (ic0 + u) * 8);
#pragma unroll
            for (int j = 0; j < 2; j++) {
                float4 q = wp[j];
                a0[4 * j + 0] = fmaf(xv[u].x, q.x, a0[4 * j + 0]);
                a0[4 * j + 1] = fmaf(xv[u].x, q.y, a0[4 * j + 1]);
                a0[4 * j + 2] = fmaf(xv[u].x, q.z, a0[4 * j + 2]);
                a0[4 * j + 3] = fmaf(xv[u].x, q.w, a0[4 * j + 3]);
                a1[4 * j + 0] = fmaf(xv[u].y, q.x, a1[4 * j + 0]);
                a1[4 * j + 1] = fmaf(xv[u].y, q.y, a1[4 * j + 1]);
                a1[4 * j + 2] = fmaf(xv[u].y, q.z, a1[4 * j + 2]);
                a1[4 * j + 3] = fmaf(xv[u].y, q.w, a1[4 * j + 3]);
            }
        }
    }
#pragma unroll
    for (int j = 0; j < 8; j++) {
        int c = g * 32 + qc * 8 + j;
        float s = bg1[c] * rsqrtf(bv1[c] + EPS);
        float bb = bb1[c] - bm1[c] * s;
        float v0 = fmaxf(fmaf(m * a0[j], s, bb), 0.f) * m;
        float v1 = fmaxf(fmaf(m * a1[j], s, bb), 0.f) * m;
        *(float2*)(op + (size_t)j * HW) = make_float2(v0, v1);
    }
}

// ---------------------------------------------------------------------------
// K2: 3x3 conv (32 -> 8 oc per block, pad 1) + BN2 + ReLU + mask
// grid = 448*4; active patches only
// ---------------------------------------------------------------------------
__global__ __launch_bounds__(224, 4) void k2(const float* __restrict__ mask,
                                             const float* __restrict__ w2,
                                             const float* __restrict__ bg2,
                                             const float* __restrict__ bb2,
                                             const float* __restrict__ bm2,
                                             const float* __restrict__ bv2) {
    __shared__ __align__(16) float ws[9216];  // [g][ic][9][8]

    const int t = threadIdx.x, blk = blockIdx.x;
    const int qc = blk & 3;
    const int bp = blk >> 2;
    const int nact = g_nact;
    if (bp * 7 >= nact) return;

    for (int e = t; e < 9216; e += 224) {
        int gg = e / 2304;
        int rem = e - gg * 2304;
        int j = rem / 288;
        int rem2 = rem - j * 288;
        int ic = rem2 / 9;
        int kk = rem2 - ic * 9;
        ws[gg * 2304 + (ic * 9 + kk) * 8 + j] = w2[((gg * 32 + qc * 8 + j) * 32 + ic) * 9 + kk];
    }
    __syncthreads();

    const int w = t >> 5, l = t & 31;
    const int base = bp * 7 + w;
    if (base >= nact) return;

    const int packed = g_list[base];
    const int pc = packed % 7;
    const int rest = packed / 7;
    const int pr = rest % 7;
    const int bgp = rest / 7;
    const int g = bgp & 3, b = bgp >> 2;
    const float m = mask[packed];

    const int r = l >> 2, cp = l & 3;
    const int grow = pr * 8 + r;
    const int col = pc * 8 + cp * 2;

    const float* mb = g_mid1 + (size_t)(b * 128 + g * 32) * HW + col;
    float* op = g_mid2 + (size_t)(b * 128 + g * 32 + qc * 8) * HW + grow * 56 + col;
    const float* wsg = ws + g * 2304;

    float a0[8], a1[8];
#pragma unroll
    for (int j = 0; j < 8; j++) { a0[j] = 0.f; a1[j] = 0.f; }

#pragma unroll 2
    for (int ic = 0; ic < 32; ic++) {
        const float* pic = mb + (size_t)ic * HW;
        float xm[3], x2[3];
        float2 xc[3];
#pragma unroll
        for (int dy = 0; dy < 3; dy++) {
            int yy = grow - 1 + dy;
            bool v = (yy >= 0) && (yy < 56);
            const float* p = pic + yy * 56;
            xm[dy] = (v && col > 0) ? p[-1] : 0.f;
            xc[dy] = v ? *(const float2*)p : make_float2(0.f, 0.f);
            x2[dy] = (v && col < 54) ? p[2] : 0.f;
        }
#pragma unroll
        for (int dy = 0; dy < 3; dy++) {
            const float4* wp = (const float4*)(wsg + (ic * 9 + dy * 3) * 8);
            float q0 = xm[dy], q1 = xc[dy].x, q2 = xc[dy].y, q3 = x2[dy];
#pragma unroll
            for (int j = 0; j < 2; j++) {
                float4 wa = wp[j];
                float4 wb = wp[2 + j];
                float4 wc = wp[4 + j];
                a0[4 * j + 0] = fmaf(q0, wa.x, fmaf(q1, wb.x, fmaf(q2, wc.x, a0[4 * j + 0])));
                a0[4 * j + 1] = fmaf(q0, wa.y, fmaf(q1, wb.y, fmaf(q2, wc.y, a0[4 * j + 1])));
                a0[4 * j + 2] = fmaf(q0, wa.z, fmaf(q1, wb.z, fmaf(q2, wc.z, a0[4 * j + 2])));
                a0[4 * j + 3] = fmaf(q0, wa.w, fmaf(q1, wb.w, fmaf(q2, wc.w, a0[4 * j + 3])));
                a1[4 * j + 0] = fmaf(q1, wa.x, fmaf(q2, wb.x, fmaf(q3, wc.x, a1[4 * j + 0])));
                a1[4 * j + 1] = fmaf(q1, wa.y, fmaf(q2, wb.y, fmaf(q3, wc.y, a1[4 * j + 1])));
                a1[4 * j + 2] = fmaf(q1, wa.z, fmaf(q2, wb.z, fmaf(q3, wc.z, a1[4 * j + 2])));
                a1[4 * j + 3] = fmaf(q1, wa.w, fmaf(q2, wb.w, fmaf(q3, wc.w, a1[4 * j + 3])));
            }
        }
    }
#pragma unroll
    for (int j = 0; j < 8; j++) {
        int c = g * 32 + qc * 8 + j;
        float s = bg2[c] * rsqrtf(bv2[c] + EPS);
        float bb = bb2[c] - bm2[c] * s;
        float v0 = fmaxf(fmaf(a0[j], s, bb), 0.f) * m;
        float v1 = fmaxf(fmaf(a1[j], s, bb), 0.f) * m;
        *(float2*)(op + (size_t)j * HW) = make_float2(v0, v1);
    }
}

// ---------------------------------------------------------------------------
// K3: 1x1 conv (32 -> 8 oc per block) + BN3 + residual + ReLU
// grid = 448*16, covers ALL patches via sorted list (homogeneous blocks)
// ---------------------------------------------------------------------------
__global__ __launch_bounds__(224, 5) void k3(const float* __restrict__ x,
                                             const float* __restrict__ mask,
                                             const float* __restrict__ w3,
                                             const float* __restrict__ bg3,
                                             const float* __restrict__ bb3,
                                             const float* __restrict__ bm3,
                                             const float* __restrict__ bv3,
                                             float* __restrict__ out) {
    __shared__ __align__(16) float ws[1024];  // [g][ic][8]

    const int t = threadIdx.x, blk = blockIdx.x;
    const int qc = blk & 15;
    const int bp = blk >> 4;

    for (int e = t; e < 1024; e += 224) {
        int gg = e >> 8;
        int rem = e & 255;
        int j = rem >> 5, ic = rem & 31;
        ws[gg * 256 + ic * 8 + j] = w3[(gg * 128 + qc * 8 + j) * 32 + ic];
    }
    __syncthreads();

    const int w = t >> 5, l = t & 31;
    const int packed = g_list[bp * 7 + w];  // always valid: 448*7 = 3136
    const int pc = packed % 7;
    const int rest = packed / 7;
    const int pr = rest % 7;
    const int bgp = rest / 7;
    const int g = bgp & 3, b = bgp >> 2;
    const float m = mask[packed];

    const int r = l >> 2, cp = l & 3;
    const int grow = pr * 8 + r;
    const int col = pc * 8 + cp * 2;

    const float* resp = x + (size_t)(b * 512 + g * 128 + qc * 8) * HW + grow * 56 + col;
    float* op = out + (size_t)(b * 512 + g * 128 + qc * 8) * HW + grow * 56 + col;

    float sc[8], bi[8];
#pragma unroll
    for (int j = 0; j < 8; j++) {
        int c = g * 128 + qc * 8 + j;
        float s = bg3[c] * rsqrtf(bv3[c] + EPS);
        sc[j] = s;
        bi[j] = bb3[c] - bm3[c] * s;
    }

    if (m != 0.f) {
        const float* mp = g_mid2 + (size_t)(b * 128 + g * 32) * HW + grow * 56 + col;
        const float* wsg = ws + g * 256;
        float a0[8], a1[8];
#pragma unroll
        for (int j = 0; j < 8; j++) { a0[j] = 0.f; a1[j] = 0.f; }

        for (int ic0 = 0; ic0 < 32; ic0 += 8) {
            float2 xv[8];
#pragma unroll
            for (int u = 0; u < 8; u++)
                xv[u] = *(const float2*)(mp + (size_t)(ic0 + u) * HW);
#pragma unroll
            for (int u = 0; u < 8; u++) {
                const float4* wp = (const float4*)(wsg + (ic0 + u) * 8);
#pragma unroll
                for (int j = 0; j < 2; j++) {
                    float4 q = wp[j];
                    a0[4 * j + 0] = fmaf(xv[u].x, q.x, a0[4 * j + 0]);
                    a0[4 * j + 1] = fmaf(xv[u].x, q.y, a0[4 * j + 1]);
                    a0[4 * j + 2] = fmaf(xv[u].x, q.z, a0[4 * j + 2]);
                    a0[4 * j + 3] = fmaf(xv[u].x, q.w, a0[4 * j + 3]);
                    a1[4 * j + 0] = fmaf(xv[u].y, q.x, a1[4 * j + 0]);
                    a1[4 * j + 1] = fmaf(xv[u].y, q.y, a1[4 * j + 1]);
                    a1[4 * j + 2] = fmaf(xv[u].y, q.z, a1[4 * j + 2]);
                    a1[4 * j + 3] = fmaf(xv[u].y, q.w, a1[4 * j + 3]);
                }
            }
        }
#pragma unroll
        for (int j = 0; j < 8; j++) {
            float2 res = *(const float2*)(resp + (size_t)j * HW);
            float v0 = fmaxf(fmaf(a0[j], sc[j], bi[j]) + res.x, 0.f);
            float v1 = fmaxf(fmaf(a1[j], sc[j], bi[j]) + res.y, 0.f);
            *(float2*)(op + (size_t)j * HW) = make_float2(v0, v1);
        }
    } else {
#pragma unroll
        for (int j = 0; j < 8; j++) {
            float2 res = *(const float2*)(resp + (size_t)j * HW);
            float v0 = fmaxf(bi[j] + res.x, 0.f);
            float v1 = fmaxf(bi[j] + res.y, 0.f);
            *(float2*)(op + (size_t)j * HW) = make_float2(v0, v1);
        }
    }
}

// ---------------------------------------------------------------------------
extern "C" void kernel_launch(void* const* d_in, const int* in_sizes, int n_in,
                              void* d_out, int out_size) {
    const float* x    = (const float*)d_in[0];
    const float* mask = (const float*)d_in[1];
    const float* w1   = (const float*)d_in[2];
    const float* g1 = (const float*)d_in[3];
    const float* b1 = (const float*)d_in[4];
    const float* m1 = (const float*)d_in[5];
    const float* v1 = (const float*)d_in[6];
    const float* w2   = (const float*)d_in[7];
    const float* g2 = (const float*)d_in[8];
    const float* b2 = (const float*)d_in[9];
    const float* m2 = (const float*)d_in[10];
    const float* v2 = (const float*)d_in[11];
    const float* w3   = (const float*)d_in[12];
    const float* g3 = (const float*)d_in[13];
    const float* b3 = (const float*)d_in[14];
    const float* m3 = (const float*)d_in[15];
    const float* v3 = (const float*)d_in[16];
    float* out = (float*)d_out;

    prep<<<1, 1024>>>(mask);
    zero_mid1<<<1480, 256>>>();

    k1<<<448 * 4, 224>>>(x, mask, w1, g1, b1, m1, v1);
    k2<<<448 * 4, 224>>>(mask, w2, g2, b2, m2, v2);
    k3<<<448 * 16, 224>>>(x, mask, w3, g3, b3, m3, v3, out);
}